// round 6
// baseline (speedup 1.0000x reference)
#include <cuda_runtime.h>

// FeatureExtractor_50165218017745  (R6: immediate-offset depth-4 chunk pipeline)
// Input : imgs_in [64, 3, 512, 512] float32 in [0,1)
// Output: [64, 96, 4, 4] float32
//
// Per-thread privatized smem histograms (u16, parity-packed: bank == lane for
// every access). Mainloop fully unrolled: each warp's 48 float4 chunks are
// constant immediate offsets from ONE base pointer (row step 4096 float4,
// channel step 65536 float4), pipelined as a 4-slot ring -> ~3-4 LDG.128
// outstanding per warp (~21-28 KB/SM in flight) to saturate DRAM.
// 16 KB smem, <=36 regs, 7 CTAs/SM -> 1024 blocks in ONE wave.
// Fused threadfence-reduction epilogue + scratch reset for graph replay.

#define BINS   32
#define BATCH  64
#define PARTS  4
#define NBLK   (BATCH * 4 * PARTS)   // 1024 blocks

__device__ unsigned g_counts[BATCH * 4 * BINS];  // zero-init; reset each run
__device__ unsigned g_done[BATCH];               // zero-init; reset each run

// bin = floor(32x) for x in [0,1): FFMA.RZ + 2^23 leaves floor(32x) in the
// low mantissa bits (exact for 0 <= 32x < 2^23).
__device__ __forceinline__ unsigned bin_of(float x) {
    return __float_as_uint(__fmaf_rz(x, 32.0f, 8388608.0f)) & 31u;
}

__device__ __forceinline__ void bump4(const float4& a, unsigned short* __restrict__ h) {
    h[bin_of(a.x) << 8] += 1u;
    h[bin_of(a.y) << 8] += 1u;
    h[bin_of(a.z) << 8] += 1u;
    h[bin_of(a.w) << 8] += 1u;
}

// chunk j (0..47) for a warp: c = j>>4, row i = (j>>1)&7, half = j&1
// float4 offset from warp base = c*65536 + i*4096 + half*32   (compile-time)
#define CHUNK_OFF(j) (((j) >> 4) * 65536 + (((j) >> 1) & 7) * 4096 + ((j) & 1) * 32)

__global__ __launch_bounds__(256, 7)
void fused_kernel(const float* __restrict__ in, float* __restrict__ out) {
    __shared__ unsigned short hist[BINS * 256];   // 16 KB
    __shared__ unsigned scratch[256 + 1];

    int bid  = blockIdx.x;                  // ((b*4 + q) * PARTS + part)
    int tid  = threadIdx.x;
    int warp = tid >> 5;
    int lane = tid & 31;

    // zero private histograms (4096 u32 words / 256 threads = 4 uint4 each)
    {
        uint4* z = (uint4*)hist;
        #pragma unroll
        for (int i = 0; i < 4; i++)
            z[tid + 256 * i] = make_uint4(0u, 0u, 0u, 0u);
    }
    __syncthreads();

    // Parity-packed slot: byte = bin*512 + (warp>>1)*128 + lane*4 + (warp&1)*2
    // -> bank = lane for every bin. Bin b's 256 counters occupy u16 range
    // [b*256, b*256+256) (permuted), so the reduction below is layout-agnostic.
    unsigned short* h = hist + ((warp >> 1) << 6) + (lane << 1) + (warp & 1);

    // Warp base pointer (float4 units):
    //   b*196608 + qy*32768 + qx*64 + w*128 + lane,  w = part*8 + warp
    {
        int part = bid & (PARTS - 1);
        int q    = (bid >> 2) & 3;
        int b    = bid >> 4;
        const float4* cb = (const float4*)in
            + b * 196608 + (q >> 1) * 32768 + (q & 1) * 64
            + (part * 8 + warp) * 128 + lane;

        float4 q0 = cb[CHUNK_OFF(0)];
        float4 q1 = cb[CHUNK_OFF(1)];
        float4 q2 = cb[CHUNK_OFF(2)];
        float4 q3 = cb[CHUNK_OFF(3)];

        #pragma unroll
        for (int t = 0; t < 11; t++) {
            float4 n0 = cb[CHUNK_OFF(4 * t + 4)];
            float4 n1 = cb[CHUNK_OFF(4 * t + 5)];
            bump4(q0, h);
            bump4(q1, h);
            q0 = n0; q1 = n1;
            float4 n2 = cb[CHUNK_OFF(4 * t + 6)];
            float4 n3 = cb[CHUNK_OFF(4 * t + 7)];
            bump4(q2, h);
            bump4(q3, h);
            q2 = n2; q3 = n3;
        }
        bump4(q0, h);
        bump4(q1, h);
        bump4(q2, h);
        bump4(q3, h);
    }
    __syncthreads();

    int b = bid >> 4;
    int q = (bid >> 2) & 3;

    // Block reduction: 8192 u16 counters -> 32 bin sums (rotated reads).
    unsigned s = 0;
    int base = (tid & 31) * 256 + (tid >> 5) * 32;
    #pragma unroll
    for (int i = 0; i < 32; i++)
        s += hist[base + ((i + tid) & 31)];
    scratch[tid] = s;
    __syncthreads();
    if (tid < 32) {
        unsigned tot = 0;
        #pragma unroll
        for (int c = 0; c < 8; c++)
            tot += scratch[tid + 32 * c];
        atomicAdd(&g_counts[((b << 2) + q) * BINS + tid], tot);
    }

    // Release counts, then bump per-batch arrival counter.
    __threadfence();
    __syncthreads();
    if (tid == 0)
        scratch[256] = atomicAdd(&g_done[b], 1u);
    __syncthreads();
    unsigned rank = scratch[256];
    if (rank != 4 * PARTS - 1) return;      // not the last block of batch b

    // ---- last block of batch b: finalize (overlapped with other batches) ----
    __threadfence();                        // acquire
    __syncthreads();

    float* s1  = (float*)hist;              // [128]: per-quadrant hist / 65536
    float* s0v = ((float*)hist) + 128;      // [32] : full-image hist / 262144

    if (tid < 128) {
        unsigned c = __ldcg(&g_counts[(b << 7) + tid]);
        s1[tid] = (float)c * (1.0f / 65536.0f);
        g_counts[(b << 7) + tid] = 0u;      // reset for next replay
    }
    __syncthreads();
    if (tid < 32)
        s0v[tid] = (s1[tid] + s1[32 + tid] + s1[64 + tid] + s1[96 + tid]) * 0.25f;
    if (tid == 0)
        g_done[b] = 0u;                     // reset for next replay
    __syncthreads();

    #pragma unroll
    for (int k = 0; k < 6; k++) {
        int idx  = tid + 256 * k;           // 0..1535
        int ch   = idx >> 4;
        int cell = idx & 15;                // y*4 + x
        float v = 0.0f;
        if (ch < 32) {
            v = s0v[ch];
        } else if (ch < 64) {
            int qq = ((cell >> 3) << 1) | ((cell >> 1) & 1);  // (y>>1)*2+(x>>1)
            v = s1[qq * BINS + (ch - 32)];
        }
        out[b * 1536 + idx] = v;
    }
}

extern "C" void kernel_launch(void* const* d_in, const int* in_sizes, int n_in,
                              void* d_out, int out_size) {
    (void)in_sizes; (void)n_in; (void)out_size;
    fused_kernel<<<NBLK, 256>>>((const float*)d_in[0], (float*)d_out);
}